// round 17
// baseline (speedup 1.0000x reference)
#include <cuda_runtime.h>
#include <cuda_bf16.h>
#include <cuda_fp16.h>
#include <cstdint>

#define B_   2
#define N_   2048
#define DIM_ 1024
#define H_   16
#define D_   64
#define BH_  (B_ * H_)
#define M_   (B_ * N_)

// ---- device scratch (allocation-free rule) ----
__device__ __half        g_f16[(size_t)M_ * DIM_];
__device__ __half        g_wq16[(size_t)3 * DIM_ * DIM_];
__device__ __nv_bfloat16 g_woh[(size_t)DIM_ * DIM_];
__device__ __nv_bfloat16 g_wol[(size_t)DIM_ * DIM_];
__device__ __half g_q[(size_t)BH_ * N_ * D_];         // q/32, fp16
__device__ __half g_k[(size_t)BH_ * N_ * D_];         // k, fp16
__device__ __half g_v[(size_t)BH_ * D_ * N_];         // v transposed, fp16
__device__ __nv_bfloat16 g_ah[(size_t)M_ * DIM_];
__device__ __nv_bfloat16 g_al[(size_t)M_ * DIM_];
__device__ unsigned g_mp[(size_t)B_ * N_ * N_ / 16];  // mask packed 2-bit

__device__ __forceinline__ unsigned b2u(__nv_bfloat162 v) {
    return *reinterpret_cast<unsigned*>(&v);
}
__device__ __forceinline__ void split2(float x0, float x1, unsigned& hi, unsigned& lo) {
    __nv_bfloat162 h2 = __floats2bfloat162_rn(x0, x1);
    __nv_bfloat162 l2 = __floats2bfloat162_rn(x0 - __bfloat162float(h2.x),
                                              x1 - __bfloat162float(h2.y));
    hi = b2u(h2); lo = b2u(l2);
}

__device__ __forceinline__ void mma16816(float* c, unsigned a0, unsigned a1,
                                         unsigned a2, unsigned a3,
                                         unsigned b0, unsigned b1) {
    asm("mma.sync.aligned.m16n8k16.row.col.f32.bf16.bf16.f32 "
        "{%0,%1,%2,%3},{%4,%5,%6,%7},{%8,%9},{%0,%1,%2,%3};\n"
        : "+f"(c[0]), "+f"(c[1]), "+f"(c[2]), "+f"(c[3])
        : "r"(a0), "r"(a1), "r"(a2), "r"(a3), "r"(b0), "r"(b1));
}
__device__ __forceinline__ void mma16816h(float* c, unsigned a0, unsigned a1,
                                          unsigned a2, unsigned a3,
                                          unsigned b0, unsigned b1) {
    asm("mma.sync.aligned.m16n8k16.row.col.f32.f16.f16.f32 "
        "{%0,%1,%2,%3},{%4,%5,%6,%7},{%8,%9},{%0,%1,%2,%3};\n"
        : "+f"(c[0]), "+f"(c[1]), "+f"(c[2]), "+f"(c[3])
        : "r"(a0), "r"(a1), "r"(a2), "r"(a3), "r"(b0), "r"(b1));
}

__device__ __forceinline__ void ldsm4(unsigned addr, unsigned& r0, unsigned& r1,
                                      unsigned& r2, unsigned& r3) {
    asm volatile("ldmatrix.sync.aligned.m8n8.x4.shared.b16 {%0,%1,%2,%3}, [%4];\n"
                 : "=r"(r0), "=r"(r1), "=r"(r2), "=r"(r3) : "r"(addr));
}

__device__ __forceinline__ void cpa16(unsigned dst, const void* src) {
    asm volatile("cp.async.cg.shared.global [%0], [%1], 16;\n" :: "r"(dst), "l"(src));
}
__device__ __forceinline__ void cp_commit() { asm volatile("cp.async.commit_group;\n"); }
__device__ __forceinline__ void cp_wait1() { asm volatile("cp.async.wait_group 1;\n"); }
__device__ __forceinline__ void cp_wait0() { asm volatile("cp.async.wait_group 0;\n"); }

__device__ __forceinline__ unsigned packf16(float lo, float hi) {
    unsigned u;
    asm("cvt.rn.f16x2.f32 %0, %1, %2;" : "=r"(u) : "f"(hi), "f"(lo));
    return u;
}
__device__ __forceinline__ unsigned u4c(const uint4& v, int c) {
    return c == 0 ? v.x : (c == 1 ? v.y : (c == 2 ? v.z : v.w));
}

// ---------------------------------------------------------------------------
// m64 x n32 x k64 warp-tile (GEMM), bf16 hi/lo split, stride 36 words.
// ---------------------------------------------------------------------------
__device__ __forceinline__ void mma_tile64(unsigned sb, int AH, int AL,
                                           int BHo, int BLo, int arow, int bcol,
                                           int lane, float c[16][4]) {
    const int m = lane >> 3, r = lane & 7;
    const unsigned paw = (unsigned)((arow + (m & 1) * 8 + r) * 36 + (m >> 1) * 4) * 4;
    const unsigned pbw = (unsigned)((bcol + (m >> 1) * 8 + r) * 36 + (m & 1) * 4) * 4;
#pragma unroll
    for (int ks = 0; ks < 4; ks++) {
        unsigned ah[4][4], al_[4][4];
#pragma unroll
        for (int mt = 0; mt < 4; mt++) {
            ldsm4(sb + AH * 4 + paw + mt * (16 * 36 * 4) + ks * 32,
                  ah[mt][0], ah[mt][1], ah[mt][2], ah[mt][3]);
            ldsm4(sb + AL * 4 + paw + mt * (16 * 36 * 4) + ks * 32,
                  al_[mt][0], al_[mt][1], al_[mt][2], al_[mt][3]);
        }
#pragma unroll
        for (int np = 0; np < 2; np++) {
            unsigned bh[4], bl[4];
            ldsm4(sb + BHo * 4 + pbw + np * (16 * 36 * 4) + ks * 32,
                  bh[0], bh[1], bh[2], bh[3]);
            ldsm4(sb + BLo * 4 + pbw + np * (16 * 36 * 4) + ks * 32,
                  bl[0], bl[1], bl[2], bl[3]);
#pragma unroll
            for (int mt = 0; mt < 4; mt++) {
                float* c0 = c[mt * 4 + np * 2 + 0];
                float* c1 = c[mt * 4 + np * 2 + 1];
                mma16816(c0, ah[mt][0], ah[mt][1], ah[mt][2], ah[mt][3], bh[0], bh[1]);
                mma16816(c0, ah[mt][0], ah[mt][1], ah[mt][2], ah[mt][3], bl[0], bl[1]);
                mma16816(c0, al_[mt][0], al_[mt][1], al_[mt][2], al_[mt][3], bh[0], bh[1]);
                mma16816(c1, ah[mt][0], ah[mt][1], ah[mt][2], ah[mt][3], bh[2], bh[3]);
                mma16816(c1, ah[mt][0], ah[mt][1], ah[mt][2], ah[mt][3], bl[2], bl[3]);
                mma16816(c1, al_[mt][0], al_[mt][1], al_[mt][2], al_[mt][3], bh[2], bh[3]);
            }
        }
    }
}

// m64 x n32 x k64 warp-tile, single fp16 (q/k/v projection).
__device__ __forceinline__ void mma_tile64_h(unsigned sb, int A, int Bo,
                                             int arow, int bcol, int lane,
                                             float c[16][4]) {
    const int m = lane >> 3, r = lane & 7;
    const unsigned paw = (unsigned)((arow + (m & 1) * 8 + r) * 36 + (m >> 1) * 4) * 4;
    const unsigned pbw = (unsigned)((bcol + (m >> 1) * 8 + r) * 36 + (m & 1) * 4) * 4;
#pragma unroll
    for (int ks = 0; ks < 4; ks++) {
        unsigned a[4][4];
#pragma unroll
        for (int mt = 0; mt < 4; mt++)
            ldsm4(sb + A * 4 + paw + mt * (16 * 36 * 4) + ks * 32,
                  a[mt][0], a[mt][1], a[mt][2], a[mt][3]);
#pragma unroll
        for (int np = 0; np < 2; np++) {
            unsigned b0, b1, b2, b3;
            ldsm4(sb + Bo * 4 + pbw + np * (16 * 36 * 4) + ks * 32, b0, b1, b2, b3);
#pragma unroll
            for (int mt = 0; mt < 4; mt++) {
                mma16816h(c[mt * 4 + np * 2 + 0], a[mt][0], a[mt][1], a[mt][2],
                          a[mt][3], b0, b1);
                mma16816h(c[mt * 4 + np * 2 + 1], a[mt][0], a[mt][1], a[mt][2],
                          a[mt][3], b2, b3);
            }
        }
    }
}

// m16 x n64 x k64 warp-tile, single fp16 A and B (attention).
__device__ __forceinline__ void mma_tile_h(unsigned sb, int A, int Bo,
                                           int arow, int lane, float c[8][4]) {
    const int m = lane >> 3, r = lane & 7;
    const unsigned pa = ((unsigned)(arow + (m & 1) * 8 + r) * 36 + (m >> 1) * 4) * 4;
    const unsigned pb = (((unsigned)((m >> 1) * 8 + r)) * 36 + (m & 1) * 4) * 4;
#pragma unroll
    for (int ks = 0; ks < 4; ks++) {
        unsigned a0, a1, a2, a3;
        ldsm4(sb + A * 4 + pa + ks * 32, a0, a1, a2, a3);
#pragma unroll
        for (int ntp = 0; ntp < 4; ntp++) {
            unsigned b0, b1, b2, b3;
            ldsm4(sb + Bo * 4 + pb + ntp * (16 * 36 * 4) + ks * 32, b0, b1, b2, b3);
            mma16816h(c[2 * ntp + 0], a0, a1, a2, a3, b0, b1);
            mma16816h(c[2 * ntp + 1], a0, a1, a2, a3, b2, b3);
        }
    }
}

// ---------------- preprocess ----------------
__global__ __launch_bounds__(256) void split_f16(const float* __restrict__ src,
                                                 __half* __restrict__ d16, int n2) {
    int i = blockIdx.x * 256 + threadIdx.x;
    if (i < n2) {
        float2 v = reinterpret_cast<const float2*>(src)[i];
        reinterpret_cast<unsigned*>(d16)[i] = packf16(v.x, v.y);
    }
}

__global__ __launch_bounds__(256) void tsplit_w(const float* __restrict__ W,
                                                __nv_bfloat16* __restrict__ dh,
                                                __nv_bfloat16* __restrict__ dl,
                                                __half* __restrict__ d16,
                                                int K, int NB) {
    __shared__ float tile[32][33];
    const int n0 = blockIdx.x * 32, k0 = blockIdx.y * 32;
    const int tx = threadIdx.x & 31, ty = threadIdx.x >> 5;
    for (int r = ty; r < 32; r += 8)
        tile[r][tx] = W[(size_t)(k0 + r) * NB + n0 + tx];
    __syncthreads();
    for (int u = threadIdx.x; u < 512; u += 256) {
        const int rr = u >> 4, c = (u & 15) * 2;
        const size_t off = ((size_t)(n0 + rr) * K + k0 + c) >> 1;
        if (dh) {
            unsigned hi, lo; split2(tile[c][rr], tile[c + 1][rr], hi, lo);
            reinterpret_cast<unsigned*>(dh)[off] = hi;
            reinterpret_cast<unsigned*>(dl)[off] = lo;
        }
        if (d16)
            reinterpret_cast<unsigned*>(d16)[off] =
                packf16(tile[c][rr], tile[c + 1][rr]);
    }
}

__global__ __launch_bounds__(256) void pack_mask(const int* __restrict__ mask,
                                                 unsigned* __restrict__ mp, int n) {
    int i = blockIdx.x * 256 + threadIdx.x;
    if (i < n) {
        const int4* s = reinterpret_cast<const int4*>(mask) + (size_t)i * 4;
        unsigned p = 0;
#pragma unroll
        for (int q = 0; q < 4; q++) {
            int4 v = s[q];
            p |= (unsigned)(v.x & 3) << (q * 8 + 0);
            p |= (unsigned)(v.y & 3) << (q * 8 + 2);
            p |= (unsigned)(v.z & 3) << (q * 8 + 4);
            p |= (unsigned)(v.w & 3) << (q * 8 + 6);
        }
        mp[i] = p;
    }
}

// ---------------- bf16 3-product GEMM (out-proj only) ----------------
#define SAH 0
#define SAL 4608
#define SBH 9216
#define SBL 11520
#define GSTG 13824

__global__ __launch_bounds__(128, 2) void mma_gemm(
    const __nv_bfloat16* __restrict__ Ah, const __nv_bfloat16* __restrict__ Al,
    const __nv_bfloat16* __restrict__ Bh, const __nv_bfloat16* __restrict__ Bl,
    float* __restrict__ Cout) {
    extern __shared__ unsigned su[];
    const unsigned sbase = (unsigned)__cvta_generic_to_shared(su);
    const int K = 1024;
    const int m0 = blockIdx.y * 128, n0 = blockIdx.x * 64;
    const int tid = threadIdx.x, lane = tid & 31, wp = tid >> 5;
    const int g = lane >> 2, t = lane & 3;
    const int rg = (wp >> 1) * 64, cg = wp & 1;

    const uint4* pAh = reinterpret_cast<const uint4*>(Ah + (size_t)m0 * K);
    const uint4* pAl = reinterpret_cast<const uint4*>(Al + (size_t)m0 * K);
    const uint4* pBh = reinterpret_cast<const uint4*>(Bh + (size_t)n0 * K);
    const uint4* pBl = reinterpret_cast<const uint4*>(Bl + (size_t)n0 * K);

    float c16[16][4] = {};

#define GLOAD(ST, K0)                                                          \
    {                                                                          \
        const int kc = (K0) >> 3;                                              \
        const unsigned base = sbase + (ST) * (GSTG * 4);                       \
        for (int idx = tid; idx < 2048; idx += 128) {                          \
            const int half = idx >> 10, r = (idx & 1023) >> 3, c = idx & 7;    \
            cpa16(base + (half ? SAL : SAH) * 4 + (r * 9 + c) * 16,            \
                  (half ? pAl : pAh) + (size_t)r * 128 + kc + c);              \
        }                                                                      \
        for (int idx = tid; idx < 1024; idx += 128) {                          \
            const int half = idx >> 9, r = (idx & 511) >> 3, c = idx & 7;      \
            cpa16(base + (half ? SBL : SBH) * 4 + (r * 9 + c) * 16,            \
                  (half ? pBl : pBh) + (size_t)r * 128 + kc + c);              \
        }                                                                      \
        cp_commit();                                                           \
    }

    GLOAD(0, 0)
    for (int it = 0; it < 16; it++) {
        if (it + 1 < 16) { GLOAD((it + 1) & 1, (it + 1) * 64) cp_wait1(); }
        else cp_wait0();
        __syncthreads();
        mma_tile64(sbase + (it & 1) * (GSTG * 4), SAH, SAL, SBH, SBL,
                   rg, cg * 32, lane, c16);
        __syncthreads();
    }
#undef GLOAD

#pragma unroll
    for (int mt = 0; mt < 4; mt++)
#pragma unroll
        for (int nt = 0; nt < 4; nt++) {
            const float* cc = c16[mt * 4 + nt];
            const int R0 = m0 + rg + mt * 16 + g;
            const int n = n0 + cg * 32 + nt * 8 + 2 * t;
            *reinterpret_cast<float2*>(&Cout[(size_t)R0 * DIM_ + n]) =
                make_float2(cc[0], cc[1]);
            *reinterpret_cast<float2*>(&Cout[(size_t)(R0 + 8) * DIM_ + n]) =
                make_float2(cc[2], cc[3]);
        }
}

// ---------------- fp16 single-product GEMM (q/k/v projection) ---------------
#define HA 0
#define HB 4608
#define HSTG 6912

__global__ __launch_bounds__(128, 3) void mma_gemm_h(
    const __half* __restrict__ A16, const __half* __restrict__ B16) {
    extern __shared__ unsigned su[];
    const unsigned sbase = (unsigned)__cvta_generic_to_shared(su);
    const int K = 1024;
    const int m0 = blockIdx.y * 128, n0 = blockIdx.x * 64;
    const int tid = threadIdx.x, lane = tid & 31, wp = tid >> 5;
    const int g = lane >> 2, t = lane & 3;
    const int rg = (wp >> 1) * 64, cg = wp & 1;

    const uint4* pA = reinterpret_cast<const uint4*>(A16 + (size_t)m0 * K);
    const uint4* pB = reinterpret_cast<const uint4*>(B16 + (size_t)n0 * K);

    float c16[16][4] = {};

#define HLOAD(ST, K0)                                                          \
    {                                                                          \
        const int kc = (K0) >> 3;                                              \
        const unsigned base = sbase + (ST) * (HSTG * 4);                       \
        for (int idx = tid; idx < 1024; idx += 128) {                          \
            const int r = idx >> 3, c = idx & 7;                               \
            cpa16(base + HA * 4 + (r * 9 + c) * 16,                            \
                  pA + (size_t)r * 128 + kc + c);                              \
        }                                                                      \
        for (int idx = tid; idx < 512; idx += 128) {                           \
            const int r = idx >> 3, c = idx & 7;                               \
            cpa16(base + HB * 4 + (r * 9 + c) * 16,                            \
                  pB + (size_t)r * 128 + kc + c);                              \
        }                                                                      \
        cp_commit();                                                           \
    }

    HLOAD(0, 0)
    for (int it = 0; it < 16; it++) {
        if (it + 1 < 16) { HLOAD((it + 1) & 1, (it + 1) * 64) cp_wait1(); }
        else cp_wait0();
        __syncthreads();
        mma_tile64_h(sbase + (it & 1) * (HSTG * 4), HA, HB, rg, cg * 32, lane, c16);
        __syncthreads();
    }
#undef HLOAD

    const int part = n0 >> 10;               // 0=q, 1=k, 2=v
    const int b = m0 >> 11;
    const int mloc = m0 & (N_ - 1);
    const int hh = (n0 & 1023) >> 6;
    const int bh = b * H_ + hh;
    if (part < 2) {
        const float SCp = (part == 0) ? 0.03125f : 1.0f;
        unsigned* uq = reinterpret_cast<unsigned*>(part == 0 ? g_q : g_k);
#pragma unroll
        for (int mt = 0; mt < 4; mt++)
#pragma unroll
            for (int nt = 0; nt < 4; nt++) {
                const float* cc = c16[mt * 4 + nt];
                const int R0 = mloc + rg + mt * 16 + g;
                const int d = cg * 32 + nt * 8 + 2 * t;
                uq[(((size_t)bh * N_ + R0) * D_ + d) >> 1] =
                    packf16(cc[0] * SCp, cc[1] * SCp);
                uq[(((size_t)bh * N_ + R0 + 8) * D_ + d) >> 1] =
                    packf16(cc[2] * SCp, cc[3] * SCp);
            }
    } else {
        // v: [bh][d][n] fp16
#pragma unroll
        for (int mt = 0; mt < 4; mt++)
#pragma unroll
            for (int nt = 0; nt < 4; nt++) {
                const float* cc = c16[mt * 4 + nt];
                const int i0v = mloc + rg + mt * 16 + g;
                const int d = cg * 32 + nt * 8 + 2 * t;
                const size_t b0 = ((size_t)bh * D_ + d) * N_;
                const size_t b1 = ((size_t)bh * D_ + d + 1) * N_;
                g_v[b0 + i0v] = __float2half(cc[0]);
                g_v[b1 + i0v] = __float2half(cc[1]);
                g_v[b0 + i0v + 8] = __float2half(cc[2]);
                g_v[b1 + i0v + 8] = __float2half(cc[3]);
            }
    }
}

// ---------------- HMMA segment attention, e recomputed ----------------------
// smem words: SQ 0 (4608), SW 4608 (4608), stages ASST + s*4608 (K +0, V +2304);
// dsh 18432 (512 f). total 18944 w = 75776 B -> 3 blocks/SM (regs <= 85).
#define SQ   0
#define SW   4608
#define ASST 9216
#define ASDS 18432

#define ACCSEG(DS, SG, E)                                                      \
    { if ((SG) == 0) (DS)[0] += (E); else if ((SG) == 1) (DS)[1] += (E);       \
      else if ((SG) == 2) (DS)[2] += (E); else (DS)[3] += (E); }

__global__ __launch_bounds__(256, 3) void attn_mma(int dummy) {
    extern __shared__ unsigned su[];
    const unsigned sbase = (unsigned)__cvta_generic_to_shared(su);
    float* dshf = reinterpret_cast<float*>(su + ASDS);
    uint4* su4 = reinterpret_cast<uint4*>(su);

    const int b = blockIdx.z, h = blockIdx.x;
    const int i0 = blockIdx.y * 128;
    const int bh = b * H_ + h;
    const int tid = threadIdx.x;
    const int lane = tid & 31, wp = tid >> 5;
    const int g = lane >> 2, t = lane & 3;
    const int r0 = wp * 16 + g, r1 = r0 + 8;
    const uint4* mp4r0 =
        reinterpret_cast<const uint4*>(g_mp) + (size_t)(b * N_ + i0 + r0) * 32;
    const uint4* mp4r1 =
        reinterpret_cast<const uint4*>(g_mp) + (size_t)(b * N_ + i0 + r1) * 32;
    const int s0 = 4 * t;

    // load Q tile (fp16)
    {
        const uint4* gq = reinterpret_cast<const uint4*>(g_q + ((size_t)bh * N_ + i0) * D_);
        for (int idx = tid; idx < 1024; idx += 256) {
            const int r = idx >> 3, c = idx & 7;
            su4[(SQ >> 2) + r * 9 + c] = gq[idx];
        }
    }

    const uint4* gk = reinterpret_cast<const uint4*>(g_k + (size_t)bh * N_ * D_);
    const uint4* gv = reinterpret_cast<const uint4*>(g_v + (size_t)bh * D_ * N_);

#define LOADK(ST, JT)                                                          \
    {                                                                          \
        const unsigned base = sbase + (ASST + (ST) * 4608) * 4;                \
        const int jr = (JT) * 512;                                             \
        for (int idx = tid; idx < 512; idx += 256) {                           \
            const int r = idx >> 3, c = idx & 7;                               \
            cpa16(base + (r * 9 + c) * 16, gk + jr + (size_t)r * 8 + c);       \
        }                                                                      \
        cp_commit();                                                           \
    }
#define LOADKV(ST, JT)                                                         \
    {                                                                          \
        const unsigned base = sbase + (ASST + (ST) * 4608) * 4;                \
        const int jr = (JT) * 512;                                             \
        const int jc = (JT) * 8;                                               \
        for (int idx = tid; idx < 512; idx += 256) {                           \
            const int r = idx >> 3, c = idx & 7;                               \
            cpa16(base + (r * 9 + c) * 16, gk + jr + (size_t)r * 8 + c);       \
        }                                                                      \
        for (int idx = tid; idx < 512; idx += 256) {                           \
            const int r = idx >> 3, c = idx & 7;                               \
            cpa16(base + 9216 + (r * 9 + c) * 16, gv + (size_t)r * 256 + jc + c); \
        }                                                                      \
        cp_commit();                                                           \
    }

    // ---------------- PASS 1: denominators only ----------------
    float ds0[4] = {0.f, 0.f, 0.f, 0.f}, ds1[4] = {0.f, 0.f, 0.f, 0.f};
    uint4 um0 = mp4r0[0], um1 = mp4r1[0];
    LOADK(0, 0)
    for (int jt = 0; jt < 32; jt++) {
        uint4 un0, un1;
        if (jt + 1 < 32) {
            LOADK((jt + 1) & 1, jt + 1)
            un0 = mp4r0[jt + 1]; un1 = mp4r1[jt + 1];
            cp_wait1();
        } else cp_wait0();
        __syncthreads();
        const int koff = ASST + (jt & 1) * 4608;
        float c8[8][4] = {};
        mma_tile_h(sbase, SQ, koff, wp * 16, lane, c8);
        // epilogue (registers only) before the barrier -> overlaps other warps
#pragma unroll
        for (int nt = 0; nt < 8; nt++) {
            const unsigned u0 = u4c(um0, nt >> 1), u1 = u4c(um1, nt >> 1);
            const int sh = s0 + ((nt & 1) << 4);
            const int ma0 = (u0 >> sh) & 3, ma1 = (u0 >> (sh + 2)) & 3;
            const int mb0 = (u1 >> sh) & 3, mb1 = (u1 >> (sh + 2)) & 3;
            const float e0 = __expf(c8[nt][0]), e1 = __expf(c8[nt][1]);
            const float e2 = __expf(c8[nt][2]), e3 = __expf(c8[nt][3]);
            ACCSEG(ds0, ma0, e0) ACCSEG(ds0, ma1, e1)
            ACCSEG(ds1, mb0, e2) ACCSEG(ds1, mb1, e3)
        }
        __syncthreads();
        um0 = un0; um1 = un1;
    }
#pragma unroll
    for (int s = 0; s < 4; s++) {
        float v0 = ds0[s], v1 = ds1[s];
        v0 += __shfl_xor_sync(0xffffffffu, v0, 1);
        v0 += __shfl_xor_sync(0xffffffffu, v0, 2);
        v1 += __shfl_xor_sync(0xffffffffu, v1, 1);
        v1 += __shfl_xor_sync(0xffffffffu, v1, 2);
        if (t == 0) { dshf[r0 * 4 + s] = v0; dshf[r1 * 4 + s] = v1; }
    }
    __syncthreads();
    for (int idx = tid; idx < 512; idx += 256) {
        const float dv = dshf[idx];
        dshf[idx] = (dv == 0.0f) ? 1.0f : 1.0f / dv;
    }
    __syncthreads();

    // ------------- PASS 2: recompute scores, w = e*inv -> O += w @ V --------
    float o8[8][4] = {};
    um0 = mp4r0[0]; um1 = mp4r1[0];
    LOADKV(0, 0)
    for (int jt = 0; jt < 32; jt++) {
        uint4 un0, un1;
        if (jt + 1 < 32) {
            LOADKV((jt + 1) & 1, jt + 1)
            un0 = mp4r0[jt + 1]; un1 = mp4r1[jt + 1];
            cp_wait1();
        } else cp_wait0();
        __syncthreads();
        const int koff = ASST + (jt & 1) * 4608;
        float c8[8][4] = {};
        mma_tile_h(sbase, SQ, koff, wp * 16, lane, c8);
#pragma unroll
        for (int nt = 0; nt < 8; nt++) {
            const unsigned u0 = u4c(um0, nt >> 1), u1 = u4c(um1, nt >> 1);
            const int sh = s0 + ((nt & 1) << 4);
            const int ma0 = (u0 >> sh) & 3, ma1 = (u0 >> (sh + 2)) & 3;
            const int mb0 = (u1 >> sh) & 3, mb1 = (u1 >> (sh + 2)) & 3;
            const float e0 = __expf(c8[nt][0]), e1 = __expf(c8[nt][1]);
            const float e2 = __expf(c8[nt][2]), e3 = __expf(c8[nt][3]);
            su[SW + r0 * 36 + nt * 4 + t] =
                packf16(e0 * dshf[r0 * 4 + ma0], e1 * dshf[r0 * 4 + ma1]);
            su[SW + r1 * 36 + nt * 4 + t] =
                packf16(e2 * dshf[r1 * 4 + mb0], e3 * dshf[r1 * 4 + mb1]);
        }
        __syncwarp();
        mma_tile_h(sbase, SW, koff + 2304, wp * 16, lane, o8);
        __syncthreads();
        um0 = un0; um1 = un1;
    }
#undef LOADK
#undef LOADKV

    // store O as split bf16
    {
        unsigned* ah = reinterpret_cast<unsigned*>(g_ah);
        unsigned* al = reinterpret_cast<unsigned*>(g_al);
#pragma unroll
        for (int nt = 0; nt < 8; nt++) {
            const int d = h * 64 + nt * 8 + 2 * t;
            unsigned hi, lo;
            split2(o8[nt][0], o8[nt][1], hi, lo);
            const size_t o0 = ((size_t)(b * N_ + i0 + r0) * DIM_ + d) >> 1;
            ah[o0] = hi; al[o0] = lo;
            split2(o8[nt][2], o8[nt][3], hi, lo);
            const size_t o1 = ((size_t)(b * N_ + i0 + r1) * DIM_ + d) >> 1;
            ah[o1] = hi; al[o1] = lo;
        }
    }
}

// ---------------------------------------------------------------------------
extern "C" void kernel_launch(void* const* d_in, const int* in_sizes, int n_in,
                              void* d_out, int out_size) {
    const float* features = (const float*)d_in[0];
    const int*   mask     = (const int*)d_in[1];
    const float* W_qkv    = (const float*)d_in[2];
    const float* W_out    = (const float*)d_in[3];
    float* out = (float*)d_out;

    cudaFuncSetAttribute(attn_mma, cudaFuncAttributeMaxDynamicSharedMemorySize, 75776);
    cudaFuncSetAttribute(mma_gemm, cudaFuncAttributeMaxDynamicSharedMemorySize, 110592);
    cudaFuncSetAttribute(mma_gemm_h, cudaFuncAttributeMaxDynamicSharedMemorySize, 55296);

    __nv_bfloat16 *woh, *wol, *ah, *al;
    __half *f16, *wq16;
    unsigned* mp;
    cudaGetSymbolAddress((void**)&f16, g_f16);
    cudaGetSymbolAddress((void**)&wq16, g_wq16);
    cudaGetSymbolAddress((void**)&woh, g_woh); cudaGetSymbolAddress((void**)&wol, g_wol);
    cudaGetSymbolAddress((void**)&ah, g_ah);   cudaGetSymbolAddress((void**)&al, g_al);
    cudaGetSymbolAddress((void**)&mp, g_mp);

    split_f16<<<(M_ * DIM_ / 2 + 255) / 256, 256>>>(features, f16, M_ * DIM_ / 2);
    tsplit_w<<<dim3(3 * DIM_ / 32, DIM_ / 32), 256>>>(W_qkv, nullptr, nullptr,
                                                      wq16, DIM_, 3 * DIM_);
    tsplit_w<<<dim3(DIM_ / 32, DIM_ / 32), 256>>>(W_out, woh, wol, nullptr,
                                                  DIM_, DIM_);
    pack_mask<<<(B_ * N_ * N_ / 16 + 255) / 256, 256>>>(mask, mp, B_ * N_ * N_ / 16);

    // q/k/v projection: fp16 single product
    mma_gemm_h<<<dim3(3 * DIM_ / 64, M_ / 128), 128, 55296>>>(f16, wq16);
    // attention
    attn_mma<<<dim3(H_, N_ / 128, B_), 256, 75776>>>(0);
    // out projection (bf16 3-product for accuracy)
    mma_gemm<<<dim3(DIM_ / 64, M_ / 128), 128, 110592>>>(ah, al, woh, wol, out);
}